// round 12
// baseline (speedup 1.0000x reference)
#include <cuda_runtime.h>
#include <cuda_fp16.h>
#include <cstdint>
#include <math.h>

// ---------------------------------------------------------------------------
// Problem dims
// ---------------------------------------------------------------------------
#define T_STEPS 128
#define B_SZ    512
#define IN_SZ   784
#define H_SZ    2048
#define OUT_SZ  10
#define MB      (T_STEPS * B_SZ)          // 65536 GEMM rows
#define BH      (B_SZ * H_SZ)             // 1048576 neurons

#define KT      784                       // K elements
#define KAP     1568                      // packed row stride in halfs: [hi|lo]

// GEMM tiling: 128x128 CTA, 4 warps (2x2) of 64x64 warp tiles (R7 base)
#define BM_T    128
#define BN_T    128
#define BK_T    16                        // K per stage = one m16n8k16 MMA
#define NSTG    49                        // 784 / 16
#define RB      48                        // smem row bytes (32B data + 16B pad)
#define REGION  (128 * RB)                // 6144 B: one of {Ahi,Alo,Bhi,Blo}
#define STAGEB  (4 * REGION)              // 24576 B per stage
#define SMEMB   (4 * STAGEB)              // 98304 B total (4 stages, 2 CTAs/SM)

// Scratch (device globals — no runtime allocation allowed)
__device__ float  g_cur[(size_t)MB * H_SZ];    // 512 MB
__device__ __half g_A[(size_t)MB * KAP];       // 205 MB packed [hi|lo] X (fp16)
__device__ __half g_B[(size_t)H_SZ * KAP];     // 6.4 MB packed [hi|lo] W1
__device__ float  g_S[(size_t)B_SZ * H_SZ];    // weighted spike sums
__device__ float  g_coef[T_STEPS];

// ---------------------------------------------------------------------------
// PTX helpers (arch-agnostic only: cp.async + mma.sync)
// ---------------------------------------------------------------------------
__device__ __forceinline__ uint32_t smem_u32(const void* p) {
    uint32_t a;
    asm("{ .reg .u64 t; cvta.to.shared.u64 t, %1; cvt.u32.u64 %0, t; }"
        : "=r"(a) : "l"(p));
    return a;
}
#define CP16(dst, src) \
    asm volatile("cp.async.cg.shared.global [%0], [%1], 16;" :: "r"(dst), "l"(src) : "memory")
#define CP_COMMIT() asm volatile("cp.async.commit_group;" ::: "memory")
#define CP_WAIT1()  asm volatile("cp.async.wait_group 1;" ::: "memory")

#define LDS32(reg, addr) \
    asm volatile("ld.shared.b32 %0, [%1];" : "=r"(reg) : "r"(addr))

// D += A*B  (m16n8k16, fp16 inputs packed f16x2 in b32 regs, fp32 accumulate)
#define MMA_F16(c, a, b)                                                       \
    asm volatile(                                                              \
        "mma.sync.aligned.m16n8k16.row.col.f32.f16.f16.f32 "                   \
        "{%0,%1,%2,%3}, {%4,%5,%6,%7}, {%8,%9}, {%0,%1,%2,%3};"                \
        : "+f"((c)[0]), "+f"((c)[1]), "+f"((c)[2]), "+f"((c)[3])               \
        : "r"((a)[0]), "r"((a)[1]), "r"((a)[2]), "r"((a)[3]),                  \
          "r"((b)[0]), "r"((b)[1]))

// ---------------------------------------------------------------------------
// Kernel 0: readout coefficients  c_t = 0.9^(127-t) - 0.8^(127-t)
// ---------------------------------------------------------------------------
__global__ void coef_kernel() {
    int t = threadIdx.x;
    if (t < T_STEPS) {
        float m = (float)(T_STEPS - 1 - t);
        g_coef[t] = powf(0.9f, m) - powf(0.8f, m);
    }
}

// ---------------------------------------------------------------------------
// Pack kernels: split fp32 -> (hi, lo) fp16 pairs (11-bit limbs)
// ---------------------------------------------------------------------------
__global__ __launch_bounds__(256)
void packA_kernel(const float* __restrict__ x) {
    size_t m = blockIdx.x;
    const float* src = x + m * IN_SZ;
    __half* dst = g_A + m * KAP;
    for (int k = threadIdx.x; k < KT; k += 256) {
        float v = src[k];
        __half h = __float2half_rn(v);
        dst[k] = h;
        dst[KT + k] = __float2half_rn(v - __half2float(h));
    }
}
__global__ __launch_bounds__(256)
void packB_kernel(const float* __restrict__ w) {
    size_t n = blockIdx.x;
    const float* src = w + n * IN_SZ;
    __half* dst = g_B + n * KAP;
    for (int k = threadIdx.x; k < KT; k += 256) {
        float v = src[k];
        __half h = __float2half_rn(v);
        dst[k] = h;
        dst[KT + k] = __float2half_rn(v - __half2float(h));
    }
}

// ---------------------------------------------------------------------------
// GEMM: CUR[65536,2048] = X @ W1^T, fp16x3 emulation on mma.sync m16n8k16.
// R7 config (128x128 CTA, 4 warps of 64x64, BK=16, 4 stages, 2 CTAs/SM, LDS32)
// + register double-buffering across stages: stage k+1 fragments are LDS'd
// before stage k's 96 MMAs so crossbar time hides under tensor time.
// (R5 tried this at the tf32 instruction wall and it was neutral; R6 proved
// fp16 has ~2x tensor headroom, so the overlap is live now.)
// Per-acc order (hh->hl->lh per stage, stages ascending) -> bit-identical.
// ---------------------------------------------------------------------------
__global__ __launch_bounds__(128, 2)
void mma_kernel() {
    extern __shared__ __align__(16) char smem[];
    const uint32_t sbase = smem_u32(smem);

    const int tid  = threadIdx.x;
    const int wid  = tid >> 5;
    const int lane = tid & 31;
    const int lq   = lane >> 2;           // 0..7
    const int lr   = lane & 3;            // 0..3
    const int warp_m = wid & 1;           // 2 strips of 64 rows
    const int warp_n = wid >> 1;          // 2 strips of 64 cols

    const int n0 = blockIdx.x * BN_T;     // x fastest -> A-tile L2 reuse
    const int m0 = blockIdx.y * BM_T;

    // ---- producer mapping: thread t owns row t of all 4 regions ----
    const int prow = tid;                 // 0..127
    const __half* ga = g_A + (size_t)(m0 + prow) * KAP;
    const __half* gb = g_B + (size_t)(n0 + prow) * KAP;
    const uint32_t prowoff = (uint32_t)prow * RB;

    float acc[4][8][4];
#pragma unroll
    for (int mi = 0; mi < 4; mi++)
#pragma unroll
        for (int ni = 0; ni < 8; ni++)
#pragma unroll
            for (int q = 0; q < 4; q++) acc[mi][ni][q] = 0.0f;

    // fragment base byte-offsets within a region
    const uint32_t a_off0 = (uint32_t)(warp_m * 64 + lq) * RB + (uint32_t)lr * 4u;
    const uint32_t b_off0 = (uint32_t)(warp_n * 64 + lq) * RB + (uint32_t)lr * 4u;

    // register fragment double-buffers (P = stage parity)
    uint32_t fah[2][4][4], fal[2][4][4], fbh[2][8][2], fbl[2][8][2];

#define LOAD_STAGE(buf, kc) do {                                               \
    uint32_t st = sbase + (uint32_t)(buf) * STAGEB;                            \
    const __half* ga_h = ga + (kc);                                            \
    const __half* gb_h = gb + (kc);                                            \
    CP16(st + 0 * REGION + prowoff,       ga_h);                               \
    CP16(st + 0 * REGION + prowoff + 16u, ga_h + 8);                           \
    CP16(st + 1 * REGION + prowoff,       ga_h + KT);                          \
    CP16(st + 1 * REGION + prowoff + 16u, ga_h + KT + 8);                      \
    CP16(st + 2 * REGION + prowoff,       gb_h);                               \
    CP16(st + 2 * REGION + prowoff + 16u, gb_h + 8);                           \
    CP16(st + 3 * REGION + prowoff,       gb_h + KT);                          \
    CP16(st + 3 * REGION + prowoff + 16u, gb_h + KT + 8);                      \
    } while (0)

// Load stage SK's fragments (64 LDS32, R7 pattern) into register buffer P.
#define PRELOAD(P, SK) do {                                                    \
    const uint32_t _st  = sbase + (uint32_t)((SK) & 3) * STAGEB;               \
    const uint32_t _sah = _st + 0 * REGION + a_off0;                           \
    const uint32_t _sal = _st + 1 * REGION + a_off0;                           \
    const uint32_t _sbh = _st + 2 * REGION + b_off0;                           \
    const uint32_t _sbl = _st + 3 * REGION + b_off0;                           \
    _Pragma("unroll")                                                          \
    for (int mi = 0; mi < 4; mi++) {                                           \
        uint32_t base = (uint32_t)mi * (16u * RB);                             \
        LDS32(fah[P][mi][0], _sah + base);                                     \
        LDS32(fah[P][mi][1], _sah + base + 8u * RB);                           \
        LDS32(fah[P][mi][2], _sah + base + 16u);                               \
        LDS32(fah[P][mi][3], _sah + base + 8u * RB + 16u);                     \
        LDS32(fal[P][mi][0], _sal + base);                                     \
        LDS32(fal[P][mi][1], _sal + base + 8u * RB);                           \
        LDS32(fal[P][mi][2], _sal + base + 16u);                               \
        LDS32(fal[P][mi][3], _sal + base + 8u * RB + 16u);                     \
    }                                                                          \
    _Pragma("unroll")                                                          \
    for (int ni = 0; ni < 8; ni++) {                                           \
        uint32_t base = (uint32_t)ni * (8u * RB);                              \
        LDS32(fbh[P][ni][0], _sbh + base);                                     \
        LDS32(fbh[P][ni][1], _sbh + base + 16u);                               \
        LDS32(fbl[P][ni][0], _sbl + base);                                     \
        LDS32(fbl[P][ni][1], _sbl + base + 16u);                               \
    } } while (0)

// All 96 MMAs for buffer P; term-outer; per-acc order hh -> hl -> lh.
#define MMA_ALL(P) do {                                                        \
    _Pragma("unroll")                                                          \
    for (int mi = 0; mi < 4; mi++)                                             \
        _Pragma("unroll")                                                      \
        for (int ni = 0; ni < 8; ni++)                                         \
            MMA_F16(acc[mi][ni], fah[P][mi], fbh[P][ni]);                      \
    _Pragma("unroll")                                                          \
    for (int mi = 0; mi < 4; mi++)                                             \
        _Pragma("unroll")                                                      \
        for (int ni = 0; ni < 8; ni++)                                         \
            MMA_F16(acc[mi][ni], fah[P][mi], fbl[P][ni]);                      \
    _Pragma("unroll")                                                          \
    for (int mi = 0; mi < 4; mi++)                                             \
        _Pragma("unroll")                                                      \
        for (int ni = 0; ni < 8; ni++)                                         \
            MMA_F16(acc[mi][ni], fal[P][mi], fbh[P][ni]);                      \
    } while (0)

    // prologue: stages 0..2 committed (3 groups outstanding)
    LOAD_STAGE(0, 0);  CP_COMMIT();
    LOAD_STAGE(1, 16); CP_COMMIT();
    LOAD_STAGE(2, 32); CP_COMMIT();

    for (int k = 0; k < NSTG; k++) {
        CP_WAIT1();                 // stages k AND k+1 resident
        __syncthreads();            // all warps done consuming stage k-1

        // prefetch stage k+3 into buffer (k+3)&3 == (k-1)&3 (freed above)
        if (k + 3 < NSTG) LOAD_STAGE((k + 3) & 3, (k + 3) * BK_T);
        CP_COMMIT();                // always commit (empty ok) to keep count

        const int P = k & 1;
        if (k == 0) PRELOAD(0, 0);          // bootstrap (once)
        if (k + 1 < NSTG) PRELOAD(P ^ 1, k + 1);  // next stage frags (hide under MMAs)
        MMA_ALL(P);                          // compute stage k
    }

    // epilogue: write C (D frag: c0=[lq][2lr], c1=[lq][2lr+1],
    //                    c2=[lq+8][2lr], c3=[lq+8][2lr+1])
#pragma unroll
    for (int mi = 0; mi < 4; mi++) {
        const int gm = m0 + warp_m * 64 + mi * 16 + lq;
        float* r0 = g_cur + (size_t)gm * H_SZ + n0 + warp_n * 64 + lr * 2;
        float* r1 = r0 + 8 * H_SZ;
#pragma unroll
        for (int ni = 0; ni < 8; ni++) {
            *(float2*)(r0 + ni * 8) = make_float2(acc[mi][ni][0], acc[mi][ni][1]);
            *(float2*)(r1 + ni * 8) = make_float2(acc[mi][ni][2], acc[mi][ni][3]);
        }
    }
#undef LOAD_STAGE
#undef PRELOAD
#undef MMA_ALL
}

// ---------------------------------------------------------------------------
// LIF scan: S = sum_t c_t * z_t   (per-neuron, state in registers)
// ---------------------------------------------------------------------------
__global__ __launch_bounds__(256)
void scan_kernel() {
    const int gid = blockIdx.x * blockDim.x + threadIdx.x;
    const float4* cur4 = (const float4*)g_cur;

    float v0 = 0.f, v1 = 0.f, v2 = 0.f, v3 = 0.f;
    float i0 = 0.f, i1 = 0.f, i2 = 0.f, i3 = 0.f;
    float s0 = 0.f, s1 = 0.f, s2 = 0.f, s3 = 0.f;

#pragma unroll 4
    for (int t = 0; t < T_STEPS; t++) {
        float4 c = __ldg(&cur4[(size_t)t * (BH / 4) + gid]);
        float coef = g_coef[t];
        float vd, id;
        vd = v0 + 0.1f * ((0.0f - v0) + i0); id = 0.8f * i0;
        if ((vd - 0.25f) > 0.0f) { v0 = 0.0f; s0 += coef; } else { v0 = vd; }
        i0 = id + c.x;
        vd = v1 + 0.1f * ((0.0f - v1) + i1); id = 0.8f * i1;
        if ((vd - 0.25f) > 0.0f) { v1 = 0.0f; s1 += coef; } else { v1 = vd; }
        i1 = id + c.y;
        vd = v2 + 0.1f * ((0.0f - v2) + i2); id = 0.8f * i2;
        if ((vd - 0.25f) > 0.0f) { v2 = 0.0f; s2 += coef; } else { v2 = vd; }
        i2 = id + c.z;
        vd = v3 + 0.1f * ((0.0f - v3) + i3); id = 0.8f * i3;
        if ((vd - 0.25f) > 0.0f) { v3 = 0.0f; s3 += coef; } else { v3 = vd; }
        i3 = id + c.w;
    }
    ((float4*)g_S)[gid] = make_float4(s0, s1, s2, s3);
}

// ---------------------------------------------------------------------------
// Readout: vo = S @ Wout^T
// ---------------------------------------------------------------------------
__global__ __launch_bounds__(256)
void readout_kernel(const float* __restrict__ Wout, float* __restrict__ out) {
    const int b = blockIdx.x;
    const int tid = threadIdx.x;
    float acc[OUT_SZ];
#pragma unroll
    for (int o = 0; o < OUT_SZ; o++) acc[o] = 0.0f;

    const float* srow = g_S + (size_t)b * H_SZ;
    for (int h = tid; h < H_SZ; h += 256) {
        float sv = srow[h];
#pragma unroll
        for (int o = 0; o < OUT_SZ; o++)
            acc[o] = fmaf(sv, __ldg(&Wout[o * H_SZ + h]), acc[o]);
    }
    __shared__ float red[OUT_SZ][8];
    const int lane = tid & 31, warp = tid >> 5;
#pragma unroll
    for (int o = 0; o < OUT_SZ; o++) {
        float v = acc[o];
#pragma unroll
        for (int off = 16; off; off >>= 1) v += __shfl_down_sync(0xffffffffu, v, off);
        if (lane == 0) red[o][warp] = v;
    }
    __syncthreads();
    if (tid < OUT_SZ) {
        float v = 0.0f;
#pragma unroll
        for (int w = 0; w < 8; w++) v += red[tid][w];
        out[b * OUT_SZ + tid] = v;
    }
}

// ---------------------------------------------------------------------------
extern "C" void kernel_launch(void* const* d_in, const int* in_sizes, int n_in,
                              void* d_out, int out_size) {
    const float* x    = (const float*)d_in[0];   // [128,512,784]
    const float* W1   = (const float*)d_in[1];   // [2048,784]
    const float* Wout = (const float*)d_in[2];   // [10,2048]
    float* out = (float*)d_out;                  // [512,10]

    coef_kernel<<<1, 128>>>();
    packA_kernel<<<MB, 256>>>(x);
    packB_kernel<<<H_SZ, 256>>>(W1);

    cudaFuncSetAttribute(mma_kernel, cudaFuncAttributeMaxDynamicSharedMemorySize, SMEMB);
    dim3 grid(H_SZ / BN_T, MB / BM_T);   // (16, 512), x fastest
    mma_kernel<<<grid, 128, SMEMB>>>();

    scan_kernel<<<BH / 4 / 256, 256>>>();
    readout_kernel<<<B_SZ, 256>>>(Wout, out);
}

// round 13
// speedup vs baseline: 1.1299x; 1.1299x over previous
#include <cuda_runtime.h>
#include <cuda_fp16.h>
#include <cstdint>
#include <math.h>

// ---------------------------------------------------------------------------
// Problem dims
// ---------------------------------------------------------------------------
#define T_STEPS 128
#define B_SZ    512
#define IN_SZ   784
#define H_SZ    2048
#define OUT_SZ  10
#define MB      (T_STEPS * B_SZ)          // 65536 GEMM rows
#define BH      (B_SZ * H_SZ)             // 1048576 neurons

#define KT      784                       // K elements
#define KAP     1568                      // packed row stride in halfs: [hi|lo]

// ---- heterogeneous split: tensor rows [0,MT), FFMA rows [MT,65536) ----
#define MT_ROWS 45568                     // 356 * 128 = 89 timestep-slices
#define NT_BLK  356                       // tensor M-blocks (128 rows)
#define NF_BLK  156                       // FFMA  M-blocks (128 rows)
#define TEN_CTAS (NT_BLK * 16)            // 5696 (128x128 tiles)
#define FF_CTAS  (NF_BLK * 32)            // 4992 (128x64 tiles)
#define TOT_CTAS (TEN_CTAS + FF_CTAS)     // 10688

// GEMM tiling (tensor path, R8-best): 128x128 CTA, 4 warps of 64x64, BK=16
#define BN_T    128
#define BK_T    16
#define NSTG    49                        // 784 / 16
#define RB      48                        // smem row bytes (32B data + 16B pad)
#define REGION  (128 * RB)                // 6144 B
#define STAGEB  (4 * REGION)              // 24576 B per stage
#define SMEMB   (4 * STAGEB)              // 98304 B (4 stages, 2 CTAs/SM)

// Scratch (device globals — no runtime allocation allowed)
__device__ float  g_cur[(size_t)MB * H_SZ];    // 512 MB
__device__ __half g_A[(size_t)MT_ROWS * KAP];  // packed [hi|lo] X (tensor rows)
__device__ __half g_B[(size_t)H_SZ * KAP];     // packed [hi|lo] W1
__device__ float  g_S[(size_t)B_SZ * H_SZ];    // weighted spike sums
__device__ float  g_coef[T_STEPS];

// ---------------------------------------------------------------------------
// PTX helpers (arch-agnostic only: cp.async + mma.sync)
// ---------------------------------------------------------------------------
__device__ __forceinline__ uint32_t smem_u32(const void* p) {
    uint32_t a;
    asm("{ .reg .u64 t; cvta.to.shared.u64 t, %1; cvt.u32.u64 %0, t; }"
        : "=r"(a) : "l"(p));
    return a;
}
#define CP16(dst, src) \
    asm volatile("cp.async.cg.shared.global [%0], [%1], 16;" :: "r"(dst), "l"(src) : "memory")
#define CP_COMMIT() asm volatile("cp.async.commit_group;" ::: "memory")
#define CP_WAIT2()  asm volatile("cp.async.wait_group 2;" ::: "memory")

#define LDS32(reg, addr) \
    asm volatile("ld.shared.b32 %0, [%1];" : "=r"(reg) : "r"(addr))

// D += A*B  (m16n8k16, fp16 inputs packed f16x2 in b32 regs, fp32 accumulate)
#define MMA_F16(c, a, b)                                                       \
    asm volatile(                                                              \
        "mma.sync.aligned.m16n8k16.row.col.f32.f16.f16.f32 "                   \
        "{%0,%1,%2,%3}, {%4,%5,%6,%7}, {%8,%9}, {%0,%1,%2,%3};"                \
        : "+f"((c)[0]), "+f"((c)[1]), "+f"((c)[2]), "+f"((c)[3])               \
        : "r"((a)[0]), "r"((a)[1]), "r"((a)[2]), "r"((a)[3]),                  \
          "r"((b)[0]), "r"((b)[1]))

// ---------------------------------------------------------------------------
// Kernel 0: readout coefficients  c_t = 0.9^(127-t) - 0.8^(127-t)
// ---------------------------------------------------------------------------
__global__ void coef_kernel() {
    int t = threadIdx.x;
    if (t < T_STEPS) {
        float m = (float)(T_STEPS - 1 - t);
        g_coef[t] = powf(0.9f, m) - powf(0.8f, m);
    }
}

// ---------------------------------------------------------------------------
// Pack kernels: split fp32 -> (hi, lo) fp16 pairs (only tensor-path rows of A)
// ---------------------------------------------------------------------------
__global__ __launch_bounds__(256)
void packA_kernel(const float* __restrict__ x) {
    size_t m = blockIdx.x;                // < MT_ROWS
    const float* src = x + m * IN_SZ;
    __half* dst = g_A + m * KAP;
    for (int k = threadIdx.x; k < KT; k += 256) {
        float v = src[k];
        __half h = __float2half_rn(v);
        dst[k] = h;
        dst[KT + k] = __float2half_rn(v - __half2float(h));
    }
}
__global__ __launch_bounds__(256)
void packB_kernel(const float* __restrict__ w) {
    size_t n = blockIdx.x;
    const float* src = w + n * IN_SZ;
    __half* dst = g_B + n * KAP;
    for (int k = threadIdx.x; k < KT; k += 256) {
        float v = src[k];
        __half h = __float2half_rn(v);
        dst[k] = h;
        dst[KT + k] = __float2half_rn(v - __half2float(h));
    }
}

// ---------------------------------------------------------------------------
// Hybrid GEMM: tensor CTAs (fp16x3 mma.sync, R8-best body) cover rows [0,MT);
// FFMA CTAs (fp32 SGEMM 128x64, R1-style) cover rows [MT, 65536).
// Roles alternate per 148-block chunk so wave-1 pairs 1 tensor + 1 FFMA CTA
// per SM: tensor pipe and fma pipe run concurrently.
// ---------------------------------------------------------------------------
__global__ __launch_bounds__(128, 2)
void mma_kernel(const float* __restrict__ X, const float* __restrict__ W1f) {
    extern __shared__ __align__(16) char smem[];
    const int tid = threadIdx.x;

    // ---- role decode: alternate chunks of 148 (wave-1 SM pairing) ----
    const int gid = blockIdx.x;
    const int c = gid / 148, p = gid - c * 148;
    int role, idx;
    if (c < 67) {
        role = c & 1;                     // even chunk -> tensor, odd -> ffma
        idx  = (c >> 1) * 148 + p;
    } else {
        int r = gid - 67 * 148;           // tail: 772 blocks
        if (r < 108) { role = 1; idx = 4884 + r; }
        else         { role = 0; idx = 5032 + (r - 108); }
    }

    if (role == 0) {
        // =================== TENSOR PATH (R8-best, verbatim) ===============
        const uint32_t sbase = smem_u32(smem);
        const int wid  = tid >> 5;
        const int lane = tid & 31;
        const int lq   = lane >> 2;
        const int lr   = lane & 3;
        const int warp_m = wid & 1;
        const int warp_n = wid >> 1;

        const int n0 = (idx & 15) * BN_T;     // x fastest -> A-tile L2 reuse
        const int m0 = (idx >> 4) * 128;

        const int prow = tid;
        const __half* ga = g_A + (size_t)(m0 + prow) * KAP;
        const __half* gb = g_B + (size_t)(n0 + prow) * KAP;
        const uint32_t prowoff = (uint32_t)prow * RB;

        float acc[4][8][4];
#pragma unroll
        for (int mi = 0; mi < 4; mi++)
#pragma unroll
            for (int ni = 0; ni < 8; ni++)
#pragma unroll
                for (int q = 0; q < 4; q++) acc[mi][ni][q] = 0.0f;

        const uint32_t a_off0 = (uint32_t)(warp_m * 64 + lq) * RB + (uint32_t)lr * 4u;
        const uint32_t b_off0 = (uint32_t)(warp_n * 64 + lq) * RB + (uint32_t)lr * 4u;

#define LOAD_STAGE(buf, kc) do {                                               \
    uint32_t st = sbase + (uint32_t)(buf) * STAGEB;                            \
    const __half* ga_h = ga + (kc);                                            \
    const __half* gb_h = gb + (kc);                                            \
    CP16(st + 0 * REGION + prowoff,       ga_h);                               \
    CP16(st + 0 * REGION + prowoff + 16u, ga_h + 8);                           \
    CP16(st + 1 * REGION + prowoff,       ga_h + KT);                          \
    CP16(st + 1 * REGION + prowoff + 16u, ga_h + KT + 8);                      \
    CP16(st + 2 * REGION + prowoff,       gb_h);                               \
    CP16(st + 2 * REGION + prowoff + 16u, gb_h + 8);                           \
    CP16(st + 3 * REGION + prowoff,       gb_h + KT);                          \
    CP16(st + 3 * REGION + prowoff + 16u, gb_h + KT + 8);                      \
    } while (0)

        LOAD_STAGE(0, 0);  CP_COMMIT();
        LOAD_STAGE(1, 16); CP_COMMIT();
        LOAD_STAGE(2, 32); CP_COMMIT();

        for (int k = 0; k < NSTG; k++) {
            CP_WAIT2();
            __syncthreads();

            if (k + 3 < NSTG) LOAD_STAGE((k + 3) & 3, (k + 3) * BK_T);
            CP_COMMIT();

            const uint32_t st = sbase + (uint32_t)(k & 3) * STAGEB;
            const uint32_t sa_h = st + 0 * REGION + a_off0;
            const uint32_t sa_l = st + 1 * REGION + a_off0;
            const uint32_t sb_h = st + 2 * REGION + b_off0;
            const uint32_t sb_l = st + 3 * REGION + b_off0;

            uint32_t ah[4][4], al[4][4], bh[8][2], bl[8][2];
#pragma unroll
            for (int mi = 0; mi < 4; mi++) {
                uint32_t base = (uint32_t)mi * (16u * RB);
                LDS32(ah[mi][0], sa_h + base);
                LDS32(ah[mi][1], sa_h + base + 8u * RB);
                LDS32(ah[mi][2], sa_h + base + 16u);
                LDS32(ah[mi][3], sa_h + base + 8u * RB + 16u);
                LDS32(al[mi][0], sa_l + base);
                LDS32(al[mi][1], sa_l + base + 8u * RB);
                LDS32(al[mi][2], sa_l + base + 16u);
                LDS32(al[mi][3], sa_l + base + 8u * RB + 16u);
            }
#pragma unroll
            for (int ni = 0; ni < 8; ni++) {
                uint32_t base = (uint32_t)ni * (8u * RB);
                LDS32(bh[ni][0], sb_h + base);
                LDS32(bh[ni][1], sb_h + base + 16u);
                LDS32(bl[ni][0], sb_l + base);
                LDS32(bl[ni][1], sb_l + base + 16u);
            }

#pragma unroll
            for (int mi = 0; mi < 4; mi++)
#pragma unroll
                for (int ni = 0; ni < 8; ni++)
                    MMA_F16(acc[mi][ni], ah[mi], bh[ni]);   // hi*hi
#pragma unroll
            for (int mi = 0; mi < 4; mi++)
#pragma unroll
                for (int ni = 0; ni < 8; ni++)
                    MMA_F16(acc[mi][ni], ah[mi], bl[ni]);   // hi*lo
#pragma unroll
            for (int mi = 0; mi < 4; mi++)
#pragma unroll
                for (int ni = 0; ni < 8; ni++)
                    MMA_F16(acc[mi][ni], al[mi], bh[ni]);   // lo*hi
        }

#pragma unroll
        for (int mi = 0; mi < 4; mi++) {
            const int gm = m0 + warp_m * 64 + mi * 16 + lq;
            float* r0 = g_cur + (size_t)gm * H_SZ + n0 + warp_n * 64 + lr * 2;
            float* r1 = r0 + 8 * H_SZ;
#pragma unroll
            for (int ni = 0; ni < 8; ni++) {
                *(float2*)(r0 + ni * 8) = make_float2(acc[mi][ni][0], acc[mi][ni][1]);
                *(float2*)(r1 + ni * 8) = make_float2(acc[mi][ni][2], acc[mi][ni][3]);
            }
        }
#undef LOAD_STAGE
    } else {
        // =================== FFMA PATH (fp32 SGEMM 128x64) =================
        const int fy = idx >> 5;              // 0..155
        const int fx = idx & 31;              // 0..31
        const int mf = MT_ROWS + fy * 128;
        const int nf = fx * 64;

        float* As = (float*)smem;             // [8][132]
        float* Bs = As + 8 * 132;             // [8][68]

        const int row  = tid;                 // A row 0..127
        const int brow = tid >> 1;            // B row 0..63
        const int bc4  = (tid & 1) * 4;
        const int tm   = (tid >> 3) * 8;      // 0..120
        const int tn   = (tid & 7) * 8;       // 0..56

        const float* xr = X   + (size_t)(mf + row)  * IN_SZ;
        const float* wr = W1f + (size_t)(nf + brow) * IN_SZ + bc4;

        float acc[8][8];
#pragma unroll
        for (int i = 0; i < 8; i++)
#pragma unroll
            for (int j = 0; j < 8; j++) acc[i][j] = 0.0f;

        for (int k0 = 0; k0 < IN_SZ; k0 += 8) {
            float4 a0 = *(const float4*)(xr + k0);
            float4 a1 = *(const float4*)(xr + k0 + 4);
            float4 b  = *(const float4*)(wr + k0);
            __syncthreads();                  // prev compute done
            As[0 * 132 + row] = a0.x; As[1 * 132 + row] = a0.y;
            As[2 * 132 + row] = a0.z; As[3 * 132 + row] = a0.w;
            As[4 * 132 + row] = a1.x; As[5 * 132 + row] = a1.y;
            As[6 * 132 + row] = a1.z; As[7 * 132 + row] = a1.w;
            Bs[(bc4 + 0) * 68 + brow] = b.x;
            Bs[(bc4 + 1) * 68 + brow] = b.y;
            Bs[(bc4 + 2) * 68 + brow] = b.z;
            Bs[(bc4 + 3) * 68 + brow] = b.w;
            __syncthreads();

#pragma unroll
            for (int kk = 0; kk < 8; kk++) {
                float ar[8], br[8];
#pragma unroll
                for (int i = 0; i < 8; i++) ar[i] = As[kk * 132 + tm + i];
#pragma unroll
                for (int j = 0; j < 8; j++) br[j] = Bs[kk * 68 + tn + j];
#pragma unroll
                for (int i = 0; i < 8; i++)
#pragma unroll
                    for (int j = 0; j < 8; j++)
                        acc[i][j] = fmaf(ar[i], br[j], acc[i][j]);
            }
        }

#pragma unroll
        for (int i = 0; i < 8; i++) {
            float* crow = g_cur + (size_t)(mf + tm + i) * H_SZ + nf + tn;
            *(float4*)(crow + 0) = make_float4(acc[i][0], acc[i][1], acc[i][2], acc[i][3]);
            *(float4*)(crow + 4) = make_float4(acc[i][4], acc[i][5], acc[i][6], acc[i][7]);
        }
    }
}

// ---------------------------------------------------------------------------
// LIF scan: S = sum_t c_t * z_t   (per-neuron, state in registers)
// ---------------------------------------------------------------------------
__global__ __launch_bounds__(256)
void scan_kernel() {
    const int gid = blockIdx.x * blockDim.x + threadIdx.x;
    const float4* cur4 = (const float4*)g_cur;

    float v0 = 0.f, v1 = 0.f, v2 = 0.f, v3 = 0.f;
    float i0 = 0.f, i1 = 0.f, i2 = 0.f, i3 = 0.f;
    float s0 = 0.f, s1 = 0.f, s2 = 0.f, s3 = 0.f;

#pragma unroll 4
    for (int t = 0; t < T_STEPS; t++) {
        float4 c = __ldg(&cur4[(size_t)t * (BH / 4) + gid]);
        float coef = g_coef[t];
        float vd, id;
        vd = v0 + 0.1f * ((0.0f - v0) + i0); id = 0.8f * i0;
        if ((vd - 0.25f) > 0.0f) { v0 = 0.0f; s0 += coef; } else { v0 = vd; }
        i0 = id + c.x;
        vd = v1 + 0.1f * ((0.0f - v1) + i1); id = 0.8f * i1;
        if ((vd - 0.25f) > 0.0f) { v1 = 0.0f; s1 += coef; } else { v1 = vd; }
        i1 = id + c.y;
        vd = v2 + 0.1f * ((0.0f - v2) + i2); id = 0.8f * i2;
        if ((vd - 0.25f) > 0.0f) { v2 = 0.0f; s2 += coef; } else { v2 = vd; }
        i2 = id + c.z;
        vd = v3 + 0.1f * ((0.0f - v3) + i3); id = 0.8f * i3;
        if ((vd - 0.25f) > 0.0f) { v3 = 0.0f; s3 += coef; } else { v3 = vd; }
        i3 = id + c.w;
    }
    ((float4*)g_S)[gid] = make_float4(s0, s1, s2, s3);
}

// ---------------------------------------------------------------------------
// Readout: vo = S @ Wout^T
// ---------------------------------------------------------------------------
__global__ __launch_bounds__(256)
void readout_kernel(const float* __restrict__ Wout, float* __restrict__ out) {
    const int b = blockIdx.x;
    const int tid = threadIdx.x;
    float acc[OUT_SZ];
#pragma unroll
    for (int o = 0; o < OUT_SZ; o++) acc[o] = 0.0f;

    const float* srow = g_S + (size_t)b * H_SZ;
    for (int h = tid; h < H_SZ; h += 256) {
        float sv = srow[h];
#pragma unroll
        for (int o = 0; o < OUT_SZ; o++)
            acc[o] = fmaf(sv, __ldg(&Wout[o * H_SZ + h]), acc[o]);
    }
    __shared__ float red[OUT_SZ][8];
    const int lane = tid & 31, warp = tid >> 5;
#pragma unroll
    for (int o = 0; o < OUT_SZ; o++) {
        float v = acc[o];
#pragma unroll
        for (int off = 16; off; off >>= 1) v += __shfl_down_sync(0xffffffffu, v, off);
        if (lane == 0) red[o][warp] = v;
    }
    __syncthreads();
    if (tid < OUT_SZ) {
        float v = 0.0f;
#pragma unroll
        for (int w = 0; w < 8; w++) v += red[tid][w];
        out[b * OUT_SZ + tid] = v;
    }
}

// ---------------------------------------------------------------------------
extern "C" void kernel_launch(void* const* d_in, const int* in_sizes, int n_in,
                              void* d_out, int out_size) {
    const float* x    = (const float*)d_in[0];   // [128,512,784]
    const float* W1   = (const float*)d_in[1];   // [2048,784]
    const float* Wout = (const float*)d_in[2];   // [10,2048]
    float* out = (float*)d_out;                  // [512,10]

    coef_kernel<<<1, 128>>>();
    packA_kernel<<<MT_ROWS, 256>>>(x);           // only tensor-path rows
    packB_kernel<<<H_SZ, 256>>>(W1);

    cudaFuncSetAttribute(mma_kernel, cudaFuncAttributeMaxDynamicSharedMemorySize, SMEMB);
    mma_kernel<<<TOT_CTAS, 128, SMEMB>>>(x, W1);

    scan_kernel<<<BH / 4 / 256, 256>>>();
    readout_kernel<<<B_SZ, 256>>>(Wout, out);
}

// round 14
// speedup vs baseline: 1.3135x; 1.1625x over previous
#include <cuda_runtime.h>
#include <cuda_fp16.h>
#include <cstdint>
#include <math.h>

// ---------------------------------------------------------------------------
// Problem dims
// ---------------------------------------------------------------------------
#define T_STEPS 128
#define B_SZ    512
#define IN_SZ   784
#define H_SZ    2048
#define OUT_SZ  10
#define MB      (T_STEPS * B_SZ)          // 65536 GEMM rows
#define BH      (B_SZ * H_SZ)             // 1048576 neurons

#define KT      784                       // K elements
#define KAP     1568                      // packed row stride in halfs: [hi|lo]

// ---- heterogeneous split (rebalanced): tensor 80%, FFMA 20% ----
#define MT_ROWS 52480                     // 410 * 128 tensor rows
#define NT_BLK  410
#define NF_BLK  102                       // 13056 FFMA rows
#define TEN_CTAS (NT_BLK * 16)            // 6560 (128x128 tiles)
#define FF_CTAS  (NF_BLK * 32)            // 3264 (128x64 tiles)
#define TOT_CTAS (TEN_CTAS + FF_CTAS)     // 9824
#define MIX3     (FF_CTAS * 3)            // 9792: region with T,T,F pattern

// GEMM tiling (tensor path, R8-best): 128x128 CTA, 4 warps of 64x64, BK=16
#define BN_T    128
#define BK_T    16
#define NSTG    49                        // 784 / 16
#define RB      48                        // smem row bytes (32B data + 16B pad)
#define REGION  (128 * RB)                // 6144 B
#define STAGEB  (4 * REGION)              // 24576 B per stage
#define SMEMB   (4 * STAGEB)              // 98304 B (4 stages, 2 CTAs/SM)

// Scratch (device globals — no runtime allocation allowed)
__device__ float  g_cur[(size_t)MB * H_SZ];    // 512 MB
__device__ __half g_A[(size_t)MT_ROWS * KAP];  // packed [hi|lo] X (tensor rows)
__device__ __half g_B[(size_t)H_SZ * KAP];     // packed [hi|lo] W1
__device__ float  g_S[(size_t)B_SZ * H_SZ];    // weighted spike sums
__device__ float  g_coef[T_STEPS];

// ---------------------------------------------------------------------------
// PTX helpers (arch-agnostic only: cp.async + mma.sync)
// ---------------------------------------------------------------------------
__device__ __forceinline__ uint32_t smem_u32(const void* p) {
    uint32_t a;
    asm("{ .reg .u64 t; cvta.to.shared.u64 t, %1; cvt.u32.u64 %0, t; }"
        : "=r"(a) : "l"(p));
    return a;
}
#define CP16(dst, src) \
    asm volatile("cp.async.cg.shared.global [%0], [%1], 16;" :: "r"(dst), "l"(src) : "memory")
#define CP_COMMIT() asm volatile("cp.async.commit_group;" ::: "memory")
#define CP_WAIT2()  asm volatile("cp.async.wait_group 2;" ::: "memory")

#define LDS32(reg, addr) \
    asm volatile("ld.shared.b32 %0, [%1];" : "=r"(reg) : "r"(addr))

// D += A*B  (m16n8k16, fp16 inputs packed f16x2 in b32 regs, fp32 accumulate)
#define MMA_F16(c, a, b)                                                       \
    asm volatile(                                                              \
        "mma.sync.aligned.m16n8k16.row.col.f32.f16.f16.f32 "                   \
        "{%0,%1,%2,%3}, {%4,%5,%6,%7}, {%8,%9}, {%0,%1,%2,%3};"                \
        : "+f"((c)[0]), "+f"((c)[1]), "+f"((c)[2]), "+f"((c)[3])               \
        : "r"((a)[0]), "r"((a)[1]), "r"((a)[2]), "r"((a)[3]),                  \
          "r"((b)[0]), "r"((b)[1]))

// ---------------------------------------------------------------------------
// Kernel 0: readout coefficients  c_t = 0.9^(127-t) - 0.8^(127-t)
// ---------------------------------------------------------------------------
__global__ void coef_kernel() {
    int t = threadIdx.x;
    if (t < T_STEPS) {
        float m = (float)(T_STEPS - 1 - t);
        g_coef[t] = powf(0.9f, m) - powf(0.8f, m);
    }
}

// ---------------------------------------------------------------------------
// Pack kernels: split fp32 -> (hi, lo) fp16 pairs (only tensor-path rows of A)
// ---------------------------------------------------------------------------
__global__ __launch_bounds__(256)
void packA_kernel(const float* __restrict__ x) {
    size_t m = blockIdx.x;                // < MT_ROWS
    const float* src = x + m * IN_SZ;
    __half* dst = g_A + m * KAP;
    for (int k = threadIdx.x; k < KT; k += 256) {
        float v = src[k];
        __half h = __float2half_rn(v);
        dst[k] = h;
        dst[KT + k] = __float2half_rn(v - __half2float(h));
    }
}
__global__ __launch_bounds__(256)
void packB_kernel(const float* __restrict__ w) {
    size_t n = blockIdx.x;
    const float* src = w + n * IN_SZ;
    __half* dst = g_B + n * KAP;
    for (int k = threadIdx.x; k < KT; k += 256) {
        float v = src[k];
        __half h = __float2half_rn(v);
        dst[k] = h;
        dst[KT + k] = __float2half_rn(v - __half2float(h));
    }
}

// ---------------------------------------------------------------------------
// Hybrid GEMM (rebalanced 80/20): tensor CTAs (fp16x3 mma.sync, R8 body) do
// rows [0,MT); FFMA CTAs (fp32 SGEMM 128x64 w/ register prefetch) do the rest.
// Roles interleave at gid%3 granularity (T,T,F) to keep both pipes fed.
// ---------------------------------------------------------------------------
__global__ __launch_bounds__(128, 2)
void mma_kernel(const float* __restrict__ X, const float* __restrict__ W1f) {
    extern __shared__ __align__(16) char smem[];
    const int tid = threadIdx.x;

    // ---- role decode: pattern T,T,F per 3 gids; tail = tensor ----
    const int gid = blockIdx.x;
    int role, idx;
    if (gid < MIX3) {
        int g3 = gid / 3, r3 = gid - g3 * 3;
        if (r3 < 2) { role = 0; idx = g3 * 2 + r3; }
        else        { role = 1; idx = g3; }
    } else {
        role = 0; idx = (FF_CTAS * 2) + (gid - MIX3);
    }

    if (role == 0) {
        // =================== TENSOR PATH (R8-best, verbatim) ===============
        const uint32_t sbase = smem_u32(smem);
        const int wid  = tid >> 5;
        const int lane = tid & 31;
        const int lq   = lane >> 2;
        const int lr   = lane & 3;
        const int warp_m = wid & 1;
        const int warp_n = wid >> 1;

        const int n0 = (idx & 15) * BN_T;     // x fastest -> A-tile L2 reuse
        const int m0 = (idx >> 4) * 128;

        const int prow = tid;
        const __half* ga = g_A + (size_t)(m0 + prow) * KAP;
        const __half* gb = g_B + (size_t)(n0 + prow) * KAP;
        const uint32_t prowoff = (uint32_t)prow * RB;

        float acc[4][8][4];
#pragma unroll
        for (int mi = 0; mi < 4; mi++)
#pragma unroll
            for (int ni = 0; ni < 8; ni++)
#pragma unroll
                for (int q = 0; q < 4; q++) acc[mi][ni][q] = 0.0f;

        const uint32_t a_off0 = (uint32_t)(warp_m * 64 + lq) * RB + (uint32_t)lr * 4u;
        const uint32_t b_off0 = (uint32_t)(warp_n * 64 + lq) * RB + (uint32_t)lr * 4u;

#define LOAD_STAGE(buf, kc) do {                                               \
    uint32_t st = sbase + (uint32_t)(buf) * STAGEB;                            \
    const __half* ga_h = ga + (kc);                                            \
    const __half* gb_h = gb + (kc);                                            \
    CP16(st + 0 * REGION + prowoff,       ga_h);                               \
    CP16(st + 0 * REGION + prowoff + 16u, ga_h + 8);                           \
    CP16(st + 1 * REGION + prowoff,       ga_h + KT);                          \
    CP16(st + 1 * REGION + prowoff + 16u, ga_h + KT + 8);                      \
    CP16(st + 2 * REGION + prowoff,       gb_h);                               \
    CP16(st + 2 * REGION + prowoff + 16u, gb_h + 8);                           \
    CP16(st + 3 * REGION + prowoff,       gb_h + KT);                          \
    CP16(st + 3 * REGION + prowoff + 16u, gb_h + KT + 8);                      \
    } while (0)

        LOAD_STAGE(0, 0);  CP_COMMIT();
        LOAD_STAGE(1, 16); CP_COMMIT();
        LOAD_STAGE(2, 32); CP_COMMIT();

        for (int k = 0; k < NSTG; k++) {
            CP_WAIT2();
            __syncthreads();

            if (k + 3 < NSTG) LOAD_STAGE((k + 3) & 3, (k + 3) * BK_T);
            CP_COMMIT();

            const uint32_t st = sbase + (uint32_t)(k & 3) * STAGEB;
            const uint32_t sa_h = st + 0 * REGION + a_off0;
            const uint32_t sa_l = st + 1 * REGION + a_off0;
            const uint32_t sb_h = st + 2 * REGION + b_off0;
            const uint32_t sb_l = st + 3 * REGION + b_off0;

            uint32_t ah[4][4], al[4][4], bh[8][2], bl[8][2];
#pragma unroll
            for (int mi = 0; mi < 4; mi++) {
                uint32_t base = (uint32_t)mi * (16u * RB);
                LDS32(ah[mi][0], sa_h + base);
                LDS32(ah[mi][1], sa_h + base + 8u * RB);
                LDS32(ah[mi][2], sa_h + base + 16u);
                LDS32(ah[mi][3], sa_h + base + 8u * RB + 16u);
                LDS32(al[mi][0], sa_l + base);
                LDS32(al[mi][1], sa_l + base + 8u * RB);
                LDS32(al[mi][2], sa_l + base + 16u);
                LDS32(al[mi][3], sa_l + base + 8u * RB + 16u);
            }
#pragma unroll
            for (int ni = 0; ni < 8; ni++) {
                uint32_t base = (uint32_t)ni * (8u * RB);
                LDS32(bh[ni][0], sb_h + base);
                LDS32(bh[ni][1], sb_h + base + 16u);
                LDS32(bl[ni][0], sb_l + base);
                LDS32(bl[ni][1], sb_l + base + 16u);
            }

#pragma unroll
            for (int mi = 0; mi < 4; mi++)
#pragma unroll
                for (int ni = 0; ni < 8; ni++)
                    MMA_F16(acc[mi][ni], ah[mi], bh[ni]);   // hi*hi
#pragma unroll
            for (int mi = 0; mi < 4; mi++)
#pragma unroll
                for (int ni = 0; ni < 8; ni++)
                    MMA_F16(acc[mi][ni], ah[mi], bl[ni]);   // hi*lo
#pragma unroll
            for (int mi = 0; mi < 4; mi++)
#pragma unroll
                for (int ni = 0; ni < 8; ni++)
                    MMA_F16(acc[mi][ni], al[mi], bh[ni]);   // lo*hi
        }

#pragma unroll
        for (int mi = 0; mi < 4; mi++) {
            const int gm = m0 + warp_m * 64 + mi * 16 + lq;
            float* r0 = g_cur + (size_t)gm * H_SZ + n0 + warp_n * 64 + lr * 2;
            float* r1 = r0 + 8 * H_SZ;
#pragma unroll
            for (int ni = 0; ni < 8; ni++) {
                *(float2*)(r0 + ni * 8) = make_float2(acc[mi][ni][0], acc[mi][ni][1]);
                *(float2*)(r1 + ni * 8) = make_float2(acc[mi][ni][2], acc[mi][ni][3]);
            }
        }
#undef LOAD_STAGE
    } else {
        // ============ FFMA PATH (fp32 SGEMM 128x64, reg prefetch) ==========
        const int fy = idx >> 5;              // 0..101
        const int fx = idx & 31;              // 0..31
        const int mf = MT_ROWS + fy * 128;
        const int nf = fx * 64;

        float* As = (float*)smem;             // [8][132]
        float* Bs = As + 8 * 132;             // [8][68]

        const int row  = tid;                 // A row 0..127
        const int brow = tid >> 1;            // B row 0..63
        const int bc4  = (tid & 1) * 4;
        const int tm   = (tid >> 3) * 8;      // 0..120
        const int tn   = (tid & 7) * 8;       // 0..56

        const float* xr = X   + (size_t)(mf + row)  * IN_SZ;
        const float* wr = W1f + (size_t)(nf + brow) * IN_SZ + bc4;

        float acc[8][8];
#pragma unroll
        for (int i = 0; i < 8; i++)
#pragma unroll
            for (int j = 0; j < 8; j++) acc[i][j] = 0.0f;

        // register prefetch: iteration k0's data loaded during k0-8's compute
        float4 a0 = *(const float4*)(xr);
        float4 a1 = *(const float4*)(xr + 4);
        float4 b  = *(const float4*)(wr);

        for (int k0 = 0; k0 < IN_SZ; k0 += 8) {
            __syncthreads();                  // prev compute done
            As[0 * 132 + row] = a0.x; As[1 * 132 + row] = a0.y;
            As[2 * 132 + row] = a0.z; As[3 * 132 + row] = a0.w;
            As[4 * 132 + row] = a1.x; As[5 * 132 + row] = a1.y;
            As[6 * 132 + row] = a1.z; As[7 * 132 + row] = a1.w;
            Bs[(bc4 + 0) * 68 + brow] = b.x;
            Bs[(bc4 + 1) * 68 + brow] = b.y;
            Bs[(bc4 + 2) * 68 + brow] = b.z;
            Bs[(bc4 + 3) * 68 + brow] = b.w;
            __syncthreads();

            if (k0 + 8 < IN_SZ) {             // prefetch next (hides under FFMAs)
                a0 = *(const float4*)(xr + k0 + 8);
                a1 = *(const float4*)(xr + k0 + 12);
                b  = *(const float4*)(wr + k0 + 8);
            }

#pragma unroll
            for (int kk = 0; kk < 8; kk++) {
                float ar[8], br[8];
#pragma unroll
                for (int i = 0; i < 8; i++) ar[i] = As[kk * 132 + tm + i];
#pragma unroll
                for (int j = 0; j < 8; j++) br[j] = Bs[kk * 68 + tn + j];
#pragma unroll
                for (int i = 0; i < 8; i++)
#pragma unroll
                    for (int j = 0; j < 8; j++)
                        acc[i][j] = fmaf(ar[i], br[j], acc[i][j]);
            }
        }

#pragma unroll
        for (int i = 0; i < 8; i++) {
            float* crow = g_cur + (size_t)(mf + tm + i) * H_SZ + nf + tn;
            *(float4*)(crow + 0) = make_float4(acc[i][0], acc[i][1], acc[i][2], acc[i][3]);
            *(float4*)(crow + 4) = make_float4(acc[i][4], acc[i][5], acc[i][6], acc[i][7]);
        }
    }
}

// ---------------------------------------------------------------------------
// LIF scan: S = sum_t c_t * z_t   (per-neuron, state in registers)
// ---------------------------------------------------------------------------
__global__ __launch_bounds__(256)
void scan_kernel() {
    const int gid = blockIdx.x * blockDim.x + threadIdx.x;
    const float4* cur4 = (const float4*)g_cur;

    float v0 = 0.f, v1 = 0.f, v2 = 0.f, v3 = 0.f;
    float i0 = 0.f, i1 = 0.f, i2 = 0.f, i3 = 0.f;
    float s0 = 0.f, s1 = 0.f, s2 = 0.f, s3 = 0.f;

#pragma unroll 4
    for (int t = 0; t < T_STEPS; t++) {
        float4 c = __ldg(&cur4[(size_t)t * (BH / 4) + gid]);
        float coef = g_coef[t];
        float vd, id;
        vd = v0 + 0.1f * ((0.0f - v0) + i0); id = 0.8f * i0;
        if ((vd - 0.25f) > 0.0f) { v0 = 0.0f; s0 += coef; } else { v0 = vd; }
        i0 = id + c.x;
        vd = v1 + 0.1f * ((0.0f - v1) + i1); id = 0.8f * i1;
        if ((vd - 0.25f) > 0.0f) { v1 = 0.0f; s1 += coef; } else { v1 = vd; }
        i1 = id + c.y;
        vd = v2 + 0.1f * ((0.0f - v2) + i2); id = 0.8f * i2;
        if ((vd - 0.25f) > 0.0f) { v2 = 0.0f; s2 += coef; } else { v2 = vd; }
        i2 = id + c.z;
        vd = v3 + 0.1f * ((0.0f - v3) + i3); id = 0.8f * i3;
        if ((vd - 0.25f) > 0.0f) { v3 = 0.0f; s3 += coef; } else { v3 = vd; }
        i3 = id + c.w;
    }
    ((float4*)g_S)[gid] = make_float4(s0, s1, s2, s3);
}

// ---------------------------------------------------------------------------
// Readout: vo = S @ Wout^T
// ---------------------------------------------------------------------------
__global__ __launch_bounds__(256)
void readout_kernel(const float* __restrict__ Wout, float* __restrict__ out) {
    const int b = blockIdx.x;
    const int tid = threadIdx.x;
    float acc[OUT_SZ];
#pragma unroll
    for (int o = 0; o < OUT_SZ; o++) acc[o] = 0.0f;

    const float* srow = g_S + (size_t)b * H_SZ;
    for (int h = tid; h < H_SZ; h += 256) {
        float sv = srow[h];
#pragma unroll
        for (int o = 0; o < OUT_SZ; o++)
            acc[o] = fmaf(sv, __ldg(&Wout[o * H_SZ + h]), acc[o]);
    }
    __shared__ float red[OUT_SZ][8];
    const int lane = tid & 31, warp = tid >> 5;
#pragma unroll
    for (int o = 0; o < OUT_SZ; o++) {
        float v = acc[o];
#pragma unroll
        for (int off = 16; off; off >>= 1) v += __shfl_down_sync(0xffffffffu, v, off);
        if (lane == 0) red[o][warp] = v;
    }
    __syncthreads();
    if (tid < OUT_SZ) {
        float v = 0.0f;
#pragma unroll
        for (int w = 0; w < 8; w++) v += red[tid][w];
        out[b * OUT_SZ + tid] = v;
    }
}

// ---------------------------------------------------------------------------
extern "C" void kernel_launch(void* const* d_in, const int* in_sizes, int n_in,
                              void* d_out, int out_size) {
    const float* x    = (const float*)d_in[0];   // [128,512,784]
    const float* W1   = (const float*)d_in[1];   // [2048,784]
    const float* Wout = (const float*)d_in[2];   // [10,2048]
    float* out = (float*)d_out;                  // [512,10]

    coef_kernel<<<1, 128>>>();
    packA_kernel<<<MT_ROWS, 256>>>(x);           // only tensor-path rows
    packB_kernel<<<H_SZ, 256>>>(W1);

    cudaFuncSetAttribute(mma_kernel, cudaFuncAttributeMaxDynamicSharedMemorySize, SMEMB);
    mma_kernel<<<TOT_CTAS, 128, SMEMB>>>(x, W1);

    scan_kernel<<<BH / 4 / 256, 256>>>();
    readout_kernel<<<B_SZ, 256>>>(Wout, out);
}

// round 15
// speedup vs baseline: 1.6119x; 1.2272x over previous
#include <cuda_runtime.h>
#include <cuda_fp16.h>
#include <cstdint>
#include <math.h>

// ---------------------------------------------------------------------------
// Problem dims
// ---------------------------------------------------------------------------
#define T_STEPS 128
#define B_SZ    512
#define IN_SZ   784
#define H_SZ    2048
#define OUT_SZ  10
#define MB      (T_STEPS * B_SZ)          // 65536 GEMM rows
#define BH      (B_SZ * H_SZ)             // 1048576 neurons

#define KT      784                       // K elements
#define KAP     1568                      // packed row stride in halfs: [hi|lo]

// GEMM tiling (R8-best): 128x128 CTA, 4 warps (2x2) of 64x64, BK=16, 4 stages
#define BN_T    128
#define BK_T    16
#define NSTG    49                        // 784 / 16
#define RB      48                        // smem row bytes (32B data + 16B pad)
#define REGION  (128 * RB)                // 6144 B
#define STAGEB  (4 * REGION)              // 24576 B per stage
#define SMEMB   (4 * STAGEB)              // 98304 B (4 stages, 2 CTAs/SM)
#define CPAD    132                       // C-tile smem row stride (floats)

// Scratch (device globals — no runtime allocation allowed)
__device__ __half g_A[(size_t)MB * KAP];       // 205 MB packed [hi|lo] X, rows b*128+t
__device__ __half g_B[(size_t)H_SZ * KAP];     // 6.4 MB packed [hi|lo] W1
__device__ float  g_S[(size_t)B_SZ * H_SZ];    // weighted spike sums
__device__ float  g_coef[T_STEPS];

// ---------------------------------------------------------------------------
// PTX helpers (arch-agnostic only: cp.async + mma.sync)
// ---------------------------------------------------------------------------
__device__ __forceinline__ uint32_t smem_u32(const void* p) {
    uint32_t a;
    asm("{ .reg .u64 t; cvta.to.shared.u64 t, %1; cvt.u32.u64 %0, t; }"
        : "=r"(a) : "l"(p));
    return a;
}
#define CP16(dst, src) \
    asm volatile("cp.async.cg.shared.global [%0], [%1], 16;" :: "r"(dst), "l"(src) : "memory")
#define CP_COMMIT() asm volatile("cp.async.commit_group;" ::: "memory")
#define CP_WAIT2()  asm volatile("cp.async.wait_group 2;" ::: "memory")
#define CP_WAIT0()  asm volatile("cp.async.wait_group 0;" ::: "memory")

#define LDS32(reg, addr) \
    asm volatile("ld.shared.b32 %0, [%1];" : "=r"(reg) : "r"(addr))

// D += A*B  (m16n8k16, fp16 inputs packed f16x2 in b32 regs, fp32 accumulate)
#define MMA_F16(c, a, b)                                                       \
    asm volatile(                                                              \
        "mma.sync.aligned.m16n8k16.row.col.f32.f16.f16.f32 "                   \
        "{%0,%1,%2,%3}, {%4,%5,%6,%7}, {%8,%9}, {%0,%1,%2,%3};"                \
        : "+f"((c)[0]), "+f"((c)[1]), "+f"((c)[2]), "+f"((c)[3])               \
        : "r"((a)[0]), "r"((a)[1]), "r"((a)[2]), "r"((a)[3]),                  \
          "r"((b)[0]), "r"((b)[1]))

// ---------------------------------------------------------------------------
// Kernel 0: readout coefficients  c_t = 0.9^(127-t) - 0.8^(127-t)
// ---------------------------------------------------------------------------
__global__ void coef_kernel() {
    int t = threadIdx.x;
    if (t < T_STEPS) {
        float m = (float)(T_STEPS - 1 - t);
        g_coef[t] = powf(0.9f, m) - powf(0.8f, m);
    }
}

// ---------------------------------------------------------------------------
// Pack kernels: split fp32 -> (hi, lo) fp16 pairs (11-bit limbs).
// A is row-PERMUTED: packed row m = b*128 + t reads x[t, b, :], so each
// 128-row GEMM tile covers all 128 timesteps of one batch element.
// ---------------------------------------------------------------------------
__global__ __launch_bounds__(256)
void packA_kernel(const float* __restrict__ x) {
    size_t m = blockIdx.x;                 // b*128 + t
    int b = (int)(m >> 7);
    int t = (int)(m & 127);
    const float* src = x + ((size_t)t * B_SZ + b) * IN_SZ;
    __half* dst = g_A + m * KAP;
    for (int k = threadIdx.x; k < KT; k += 256) {
        float v = src[k];
        __half h = __float2half_rn(v);
        dst[k] = h;
        dst[KT + k] = __float2half_rn(v - __half2float(h));
    }
}
__global__ __launch_bounds__(256)
void packB_kernel(const float* __restrict__ w) {
    size_t n = blockIdx.x;
    const float* src = w + n * IN_SZ;
    __half* dst = g_B + n * KAP;
    for (int k = threadIdx.x; k < KT; k += 256) {
        float v = src[k];
        __half h = __float2half_rn(v);
        dst[k] = h;
        dst[KT + k] = __float2half_rn(v - __half2float(h));
    }
}

// ---------------------------------------------------------------------------
// Fused GEMM + LIF scan. GEMM body is R8-best verbatim (fp16x3 mma.sync,
// 128x128 CTA, 4 warps of 64x64, BK=16, 4-stage cp.async, 2 CTAs/SM).
// Tile = (one batch element b: t=0..127) x (128 hidden units). Epilogue dumps
// the C tile to smem and runs the LIF scan in-CTA, writing S[b, h] directly.
// No g_cur (saves 1 GB of DRAM round-trip + the separate scan kernel).
// GEMM K-order and scan op order unchanged -> bit-identical results.
// ---------------------------------------------------------------------------
__global__ __launch_bounds__(128, 2)
void mma_kernel() {
    extern __shared__ __align__(16) char smem[];
    const uint32_t sbase = smem_u32(smem);

    const int tid  = threadIdx.x;
    const int wid  = tid >> 5;
    const int lane = tid & 31;
    const int lq   = lane >> 2;           // 0..7
    const int lr   = lane & 3;            // 0..3
    const int warp_m = wid & 1;           // 2 strips of 64 rows (t)
    const int warp_n = wid >> 1;          // 2 strips of 64 cols (h)

    const int n0 = blockIdx.x * BN_T;     // x fastest -> A-tile L2 reuse
    const int m0 = blockIdx.y * 128;      // = b * 128
    const int bidx = blockIdx.y;          // batch element

    // ---- producer mapping: thread t owns row t of all 4 regions ----
    const int prow = tid;                 // 0..127
    const __half* ga = g_A + (size_t)(m0 + prow) * KAP;
    const __half* gb = g_B + (size_t)(n0 + prow) * KAP;
    const uint32_t prowoff = (uint32_t)prow * RB;

    float acc[4][8][4];
#pragma unroll
    for (int mi = 0; mi < 4; mi++)
#pragma unroll
        for (int ni = 0; ni < 8; ni++)
#pragma unroll
            for (int q = 0; q < 4; q++) acc[mi][ni][q] = 0.0f;

    // fragment base byte-offsets within a region
    const uint32_t a_off0 = (uint32_t)(warp_m * 64 + lq) * RB + (uint32_t)lr * 4u;
    const uint32_t b_off0 = (uint32_t)(warp_n * 64 + lq) * RB + (uint32_t)lr * 4u;

#define LOAD_STAGE(buf, kc) do {                                               \
    uint32_t st = sbase + (uint32_t)(buf) * STAGEB;                            \
    const __half* ga_h = ga + (kc);                                            \
    const __half* gb_h = gb + (kc);                                            \
    CP16(st + 0 * REGION + prowoff,       ga_h);                               \
    CP16(st + 0 * REGION + prowoff + 16u, ga_h + 8);                           \
    CP16(st + 1 * REGION + prowoff,       ga_h + KT);                          \
    CP16(st + 1 * REGION + prowoff + 16u, ga_h + KT + 8);                      \
    CP16(st + 2 * REGION + prowoff,       gb_h);                               \
    CP16(st + 2 * REGION + prowoff + 16u, gb_h + 8);                           \
    CP16(st + 3 * REGION + prowoff,       gb_h + KT);                          \
    CP16(st + 3 * REGION + prowoff + 16u, gb_h + KT + 8);                      \
    } while (0)

    // prologue: stages 0..2 committed (3 groups outstanding)
    LOAD_STAGE(0, 0);  CP_COMMIT();
    LOAD_STAGE(1, 16); CP_COMMIT();
    LOAD_STAGE(2, 32); CP_COMMIT();

    for (int k = 0; k < NSTG; k++) {
        CP_WAIT2();                 // stage k resident (<=2 groups outstanding)
        __syncthreads();            // everyone done with stage k-1 buffer

        // prefetch stage k+3 into buffer (k+3)&3 == (k-1)&3 (freed above)
        if (k + 3 < NSTG) LOAD_STAGE((k + 3) & 3, (k + 3) * BK_T);
        CP_COMMIT();                // always commit (empty ok) to keep count

        const uint32_t st = sbase + (uint32_t)(k & 3) * STAGEB;
        const uint32_t sa_h = st + 0 * REGION + a_off0;
        const uint32_t sa_l = st + 1 * REGION + a_off0;
        const uint32_t sb_h = st + 2 * REGION + b_off0;
        const uint32_t sb_l = st + 3 * REGION + b_off0;

        // ---- preload all fragments (64 LDS32) ----
        uint32_t ah[4][4], al[4][4], bh[8][2], bl[8][2];
#pragma unroll
        for (int mi = 0; mi < 4; mi++) {
            uint32_t base = (uint32_t)mi * (16u * RB);
            LDS32(ah[mi][0], sa_h + base);
            LDS32(ah[mi][1], sa_h + base + 8u * RB);
            LDS32(ah[mi][2], sa_h + base + 16u);
            LDS32(ah[mi][3], sa_h + base + 8u * RB + 16u);
            LDS32(al[mi][0], sa_l + base);
            LDS32(al[mi][1], sa_l + base + 8u * RB);
            LDS32(al[mi][2], sa_l + base + 16u);
            LDS32(al[mi][3], sa_l + base + 8u * RB + 16u);
        }
#pragma unroll
        for (int ni = 0; ni < 8; ni++) {
            uint32_t base = (uint32_t)ni * (8u * RB);
            LDS32(bh[ni][0], sb_h + base);
            LDS32(bh[ni][1], sb_h + base + 16u);
            LDS32(bl[ni][0], sb_l + base);
            LDS32(bl[ni][1], sb_l + base + 16u);
        }

        // ---- 96 MMAs: term-outer; per-acc order hh -> hl -> lh ----
#pragma unroll
        for (int mi = 0; mi < 4; mi++)
#pragma unroll
            for (int ni = 0; ni < 8; ni++)
                MMA_F16(acc[mi][ni], ah[mi], bh[ni]);   // hi*hi
#pragma unroll
        for (int mi = 0; mi < 4; mi++)
#pragma unroll
            for (int ni = 0; ni < 8; ni++)
                MMA_F16(acc[mi][ni], ah[mi], bl[ni]);   // hi*lo
#pragma unroll
        for (int mi = 0; mi < 4; mi++)
#pragma unroll
            for (int ni = 0; ni < 8; ni++)
                MMA_F16(acc[mi][ni], al[mi], bh[ni]);   // lo*hi
    }

    // ======================= fused epilogue: LIF scan =======================
    // Drain any in-flight (empty) cp.async groups, then reuse stage smem as
    // the C tile [128 t][CPAD] floats (67.6 KB <= 96 KB).
    CP_WAIT0();
    __syncthreads();

    float* Csm = (float*)smem;
#pragma unroll
    for (int mi = 0; mi < 4; mi++) {
        const int r0 = warp_m * 64 + mi * 16 + lq;       // t row
        const int c0 = warp_n * 64 + lr * 2;             // h col base
        float* w0 = Csm + (size_t)r0 * CPAD + c0;
        float* w1 = Csm + (size_t)(r0 + 8) * CPAD + c0;
#pragma unroll
        for (int ni = 0; ni < 8; ni++) {
            *(float2*)(w0 + ni * 8) = make_float2(acc[mi][ni][0], acc[mi][ni][1]);
            *(float2*)(w1 + ni * 8) = make_float2(acc[mi][ni][2], acc[mi][ni][3]);
        }
    }
    __syncthreads();

    // thread j scans hidden unit (n0 + j) of batch element bidx over t=0..127
    {
        float v = 0.0f, ii = 0.0f, s = 0.0f;
        const float* col = Csm + tid;
        for (int t = 0; t < T_STEPS; t++) {
            float c = col[(size_t)t * CPAD];
            float coef = g_coef[t];
            float vd = v + 0.1f * ((0.0f - v) + ii);
            float id = 0.8f * ii;
            if ((vd - 0.25f) > 0.0f) { v = 0.0f; s += coef; } else { v = vd; }
            ii = id + c;
        }
        g_S[(size_t)bidx * H_SZ + n0 + tid] = s;
    }
#undef LOAD_STAGE
}

// ---------------------------------------------------------------------------
// Readout: vo = S @ Wout^T
// ---------------------------------------------------------------------------
__global__ __launch_bounds__(256)
void readout_kernel(const float* __restrict__ Wout, float* __restrict__ out) {
    const int b = blockIdx.x;
    const int tid = threadIdx.x;
    float acc[OUT_SZ];
#pragma unroll
    for (int o = 0; o < OUT_SZ; o++) acc[o] = 0.0f;

    const float* srow = g_S + (size_t)b * H_SZ;
    for (int h = tid; h < H_SZ; h += 256) {
        float sv = srow[h];
#pragma unroll
        for (int o = 0; o < OUT_SZ; o++)
            acc[o] = fmaf(sv, __ldg(&Wout[o * H_SZ + h]), acc[o]);
    }
    __shared__ float red[OUT_SZ][8];
    const int lane = tid & 31, warp = tid >> 5;
#pragma unroll
    for (int o = 0; o < OUT_SZ; o++) {
        float v = acc[o];
#pragma unroll
        for (int off = 16; off; off >>= 1) v += __shfl_down_sync(0xffffffffu, v, off);
        if (lane == 0) red[o][warp] = v;
    }
    __syncthreads();
    if (tid < OUT_SZ) {
        float v = 0.0f;
#pragma unroll
        for (int w = 0; w < 8; w++) v += red[tid][w];
        out[b * OUT_SZ + tid] = v;
    }
}

// ---------------------------------------------------------------------------
extern "C" void kernel_launch(void* const* d_in, const int* in_sizes, int n_in,
                              void* d_out, int out_size) {
    const float* x    = (const float*)d_in[0];   // [128,512,784]
    const float* W1   = (const float*)d_in[1];   // [2048,784]
    const float* Wout = (const float*)d_in[2];   // [10,2048]
    float* out = (float*)d_out;                  // [512,10]

    coef_kernel<<<1, 128>>>();
    packA_kernel<<<MB, 256>>>(x);
    packB_kernel<<<H_SZ, 256>>>(W1);

    cudaFuncSetAttribute(mma_kernel, cudaFuncAttributeMaxDynamicSharedMemorySize, SMEMB);
    dim3 grid(H_SZ / BN_T, B_SZ);        // (16, 512), x fastest
    mma_kernel<<<grid, 128, SMEMB>>>();

    readout_kernel<<<B_SZ, 256>>>(Wout, out);
}